// round 1
// baseline (speedup 1.0000x reference)
#include <cuda_runtime.h>
#include <cuda_bf16.h>

#define NEGV (-9000000000000000.0f)
#define LEAKY 0.01f
#define SPLITS 8
#define THREADS 256
#define MAXB 128

// scratch: partial (max, sumexp) per (b, chunk), and final (max, 1/sum) per b
__device__ float2 g_partials[MAXB * SPLITS];
__device__ float2 g_final[MAXB];

__device__ __forceinline__ void sm_combine(float& m, float& s, float mo, float so) {
    float mn = fmaxf(m, mo);
    s = s * __expf(m - mn) + so * __expf(mo - mn);
    m = mn;
}

__global__ __launch_bounds__(THREADS) void pass1(
    const float* __restrict__ x, const float* __restrict__ raw_x,
    const float* __restrict__ a, const float* __restrict__ mask,
    const int* __restrict__ node_index, const int* __restrict__ type_index,
    float* __restrict__ out, int B, int N)
{
    int b = blockIdx.x / SPLITS;
    int chunk = blockIdx.x - b * SPLITS;
    int tid = threadIdx.x;

    __shared__ float4 w4[16];        // a[t, 64:128] for the raw_x dot
    __shared__ float c_sh;           // constant term dot(x[b,node,:], a[t,0:64])
    __shared__ float red_m[THREADS / 32], red_s[THREADS / 32];

    int t = type_index[b];
    if (tid < 16)
        w4[tid] = reinterpret_cast<const float4*>(a + t * 128 + 64)[tid];
    if (tid < 32) {
        const float* xr = x + (size_t)b * N * 64 + (size_t)node_index[0] * 64;
        const float* wa = a + t * 128;
        float s = xr[tid] * wa[tid] + xr[tid + 32] * wa[tid + 32];
        #pragma unroll
        for (int off = 16; off; off >>= 1)
            s += __shfl_xor_sync(0xffffffffu, s, off);
        if (tid == 0) c_sh = s;
    }
    __syncthreads();
    float c = c_sh;

    int rows = (N + SPLITS - 1) / SPLITS;
    int n0 = chunk * rows;
    int n1 = min(n0 + rows, N);

    float m = NEGV, s = 0.0f;
    const float4* base = reinterpret_cast<const float4*>(raw_x + (size_t)b * N * 64);

    for (int n = n0 + tid; n < n1; n += THREADS) {
        const float4* r = base + (size_t)n * 16;
        float e = c;
        #pragma unroll
        for (int j = 0; j < 16; j++) {
            float4 v = r[j];
            float4 w = w4[j];
            e += v.x * w.x;
            e += v.y * w.y;
            e += v.z * w.z;
            e += v.w * w.w;
        }
        e = e > 0.0f ? e : LEAKY * e;
        float val = (mask[n] > 0.0f) ? e : NEGV;
        out[(size_t)b * N + n] = val;
        // online softmax update
        float mn = fmaxf(m, val);
        s = s * __expf(m - mn) + __expf(val - mn);
        m = mn;
    }

    // warp reduce (m, s)
    #pragma unroll
    for (int off = 16; off; off >>= 1) {
        float mo = __shfl_xor_sync(0xffffffffu, m, off);
        float so = __shfl_xor_sync(0xffffffffu, s, off);
        sm_combine(m, s, mo, so);
    }
    int w = tid >> 5;
    if ((tid & 31) == 0) { red_m[w] = m; red_s[w] = s; }
    __syncthreads();
    if (tid < 32) {
        m = (tid < THREADS / 32) ? red_m[tid] : NEGV;
        s = (tid < THREADS / 32) ? red_s[tid] : 0.0f;
        #pragma unroll
        for (int off = 16; off; off >>= 1) {
            float mo = __shfl_xor_sync(0xffffffffu, m, off);
            float so = __shfl_xor_sync(0xffffffffu, s, off);
            sm_combine(m, s, mo, so);
        }
        if (tid == 0) g_partials[b * SPLITS + chunk] = make_float2(m, s);
    }
}

__global__ void pass2(int B)
{
    int b = threadIdx.x;
    if (b >= B) return;
    float m = NEGV, s = 0.0f;
    #pragma unroll
    for (int i = 0; i < SPLITS; i++) {
        float2 p = g_partials[b * SPLITS + i];
        sm_combine(m, s, p.x, p.y);
    }
    g_final[b] = make_float2(m, 1.0f / s);
}

__global__ __launch_bounds__(THREADS) void pass3(
    const float* __restrict__ mask, float* __restrict__ out, int B, int N)
{
    int b = blockIdx.x / SPLITS;
    int chunk = blockIdx.x - b * SPLITS;
    int tid = threadIdx.x;
    float2 f = g_final[b];

    int rows = (N + SPLITS - 1) / SPLITS;
    int n0 = chunk * rows;
    int n1 = min(n0 + rows, N);

    for (int n = n0 + tid; n < n1; n += THREADS) {
        size_t idx = (size_t)b * N + n;
        float v = out[idx];
        out[idx] = __expf(v - f.x) * f.y * mask[n];
    }
}

extern "C" void kernel_launch(void* const* d_in, const int* in_sizes, int n_in,
                              void* d_out, int out_size)
{
    const float* x          = (const float*)d_in[0];
    const float* raw_x      = (const float*)d_in[1];
    const float* a          = (const float*)d_in[2];
    const float* mask       = (const float*)d_in[3];
    const int*   node_index = (const int*)d_in[4];
    const int*   type_index = (const int*)d_in[5];
    float* out = (float*)d_out;

    int N = in_sizes[3];   // adj_mask element count
    int B = in_sizes[5];   // type_index element count

    pass1<<<B * SPLITS, THREADS>>>(x, raw_x, a, mask, node_index, type_index, out, B, N);
    pass2<<<1, 256>>>(B);
    pass3<<<B * SPLITS, THREADS>>>(mask, out, B, N);
}

// round 2
// speedup vs baseline: 1.1529x; 1.1529x over previous
#include <cuda_runtime.h>
#include <cuda_bf16.h>

#define NEGV (-9000000000000000.0f)
#define LEAKY 0.01f
#define SPLITS 16
#define THREADS 256
#define NWARPS (THREADS / 32)
#define MAXB 128

// scratch: partial (max, sumexp) per (b, chunk), and final (max, 1/sum) per b
__device__ float2 g_partials[MAXB * SPLITS];
__device__ float2 g_final[MAXB];

__device__ __forceinline__ void sm_combine(float& m, float& s, float mo, float so) {
    float mn = fmaxf(m, mo);
    s = s * __expf(m - mn) + so * __expf(mo - mn);
    m = mn;
}

__global__ __launch_bounds__(THREADS) void pass1(
    const float* __restrict__ x, const float* __restrict__ raw_x,
    const float* __restrict__ a, const float* __restrict__ mask,
    const int* __restrict__ node_index, const int* __restrict__ type_index,
    float* __restrict__ out, int B, int N)
{
    int b = blockIdx.x / SPLITS;
    int chunk = blockIdx.x - b * SPLITS;
    int tid = threadIdx.x;
    int lane = tid & 31, warp = tid >> 5;
    int q = lane & 15;              // position within row (float4 index)
    int half = lane >> 4;           // which of the 2 rows per iteration

    __shared__ float4 w4s[16];      // a[t, 64:128]
    __shared__ float c_sh;          // dot(x[b,node,:], a[t,0:64])
    __shared__ float red_m[NWARPS], red_s[NWARPS];

    int t = type_index[b];
    if (tid < 16)
        w4s[tid] = reinterpret_cast<const float4*>(a + t * 128 + 64)[tid];
    if (tid < 32) {
        const float* xr = x + (size_t)b * N * 64 + (size_t)node_index[0] * 64;
        const float* wa = a + t * 128;
        float s = xr[lane] * wa[lane] + xr[lane + 32] * wa[lane + 32];
        #pragma unroll
        for (int off = 16; off; off >>= 1)
            s += __shfl_xor_sync(0xffffffffu, s, off);
        if (lane == 0) c_sh = s;
    }
    __syncthreads();
    float c = c_sh;
    float4 w = w4s[q];              // weight fragment lives in registers

    int rows = (N + SPLITS - 1) / SPLITS;
    int n0 = chunk * rows;
    int n1 = min(n0 + rows, N);

    const float4* base = reinterpret_cast<const float4*>(raw_x + (size_t)b * N * 64);

    float m = NEGV, s = 0.0f;

    // each warp processes tiles of 32 consecutive rows
    for (int tile = n0 + warp * 32; tile < n1; tile += NWARPS * 32) {
        float held = NEGV;
        #pragma unroll 4
        for (int p = 0; p < 16; p++) {
            int n = tile + 2 * p + half;
            int nc = min(n, N - 1);                 // clamp tail loads in-bounds
            float4 v = base[(size_t)nc * 16 + q];   // warp-contiguous 512B
            float e = v.x * w.x + v.y * w.y + v.z * w.z + v.w * w.w;
            // reduce across the 16-lane row group
            e += __shfl_xor_sync(0xffffffffu, e, 1);
            e += __shfl_xor_sync(0xffffffffu, e, 2);
            e += __shfl_xor_sync(0xffffffffu, e, 4);
            e += __shfl_xor_sync(0xffffffffu, e, 8);
            if (q == p) held = e + c;
        }
        // lane (q,half) now holds row tile + 2q + half
        int nh = tile + 2 * q + half;
        if (nh < n1) {
            float e = held;
            e = e > 0.0f ? e : LEAKY * e;
            float val = (mask[nh] > 0.0f) ? e : NEGV;   // coalesced mask read
            out[(size_t)b * N + nh] = val;              // coalesced 128B store
            float mn = fmaxf(m, val);
            s = s * __expf(m - mn) + __expf(val - mn);
            m = mn;
        }
    }

    // warp reduce (m, s)
    #pragma unroll
    for (int off = 16; off; off >>= 1) {
        float mo = __shfl_xor_sync(0xffffffffu, m, off);
        float so = __shfl_xor_sync(0xffffffffu, s, off);
        sm_combine(m, s, mo, so);
    }
    if (lane == 0) { red_m[warp] = m; red_s[warp] = s; }
    __syncthreads();
    if (tid < 32) {
        m = (lane < NWARPS) ? red_m[lane] : NEGV;
        s = (lane < NWARPS) ? red_s[lane] : 0.0f;
        #pragma unroll
        for (int off = 16; off; off >>= 1) {
            float mo = __shfl_xor_sync(0xffffffffu, m, off);
            float so = __shfl_xor_sync(0xffffffffu, s, off);
            sm_combine(m, s, mo, so);
        }
        if (lane == 0) g_partials[b * SPLITS + chunk] = make_float2(m, s);
    }
}

__global__ void pass2(int B)
{
    int b = threadIdx.x;
    if (b >= B) return;
    float m = NEGV, s = 0.0f;
    #pragma unroll
    for (int i = 0; i < SPLITS; i++) {
        float2 p = g_partials[b * SPLITS + i];
        sm_combine(m, s, p.x, p.y);
    }
    g_final[b] = make_float2(m, 1.0f / s);
}

__global__ __launch_bounds__(THREADS) void pass3(
    const float* __restrict__ mask, float* __restrict__ out, int B, int N)
{
    int b = blockIdx.x / SPLITS;
    int chunk = blockIdx.x - b * SPLITS;
    int tid = threadIdx.x;
    float2 f = g_final[b];

    int rows = (N + SPLITS - 1) / SPLITS;
    int n0 = chunk * rows;
    int n1 = min(n0 + rows, N);

    for (int n = n0 + tid; n < n1; n += THREADS) {
        size_t idx = (size_t)b * N + n;
        float v = out[idx];
        out[idx] = __expf(v - f.x) * f.y * mask[n];
    }
}

extern "C" void kernel_launch(void* const* d_in, const int* in_sizes, int n_in,
                              void* d_out, int out_size)
{
    const float* x          = (const float*)d_in[0];
    const float* raw_x      = (const float*)d_in[1];
    const float* a          = (const float*)d_in[2];
    const float* mask       = (const float*)d_in[3];
    const int*   node_index = (const int*)d_in[4];
    const int*   type_index = (const int*)d_in[5];
    float* out = (float*)d_out;

    int N = in_sizes[3];   // adj_mask element count
    int B = in_sizes[5];   // type_index element count

    pass1<<<B * SPLITS, THREADS>>>(x, raw_x, a, mask, node_index, type_index, out, B, N);
    pass2<<<1, 256>>>(B);
    pass3<<<B * SPLITS, THREADS>>>(mask, out, B, N);
}

// round 3
// speedup vs baseline: 1.4848x; 1.2879x over previous
#include <cuda_runtime.h>
#include <cuda_bf16.h>

#define NEGV (-9000000000000000.0f)
#define LEAKY 0.01f
#define SPLITS 16
#define THREADS 256
#define NWARPS (THREADS / 32)
#define MAXB 128

__device__ float2 g_partials[MAXB * SPLITS];
__device__ float2 g_final[MAXB];

__device__ __forceinline__ void sm_combine(float& m, float& s, float mo, float so) {
    float mn = fmaxf(m, mo);
    s = s * __expf(m - mn) + so * __expf(mo - mn);
    m = mn;
}

__global__ __launch_bounds__(THREADS) void pass1(
    const float* __restrict__ x, const float* __restrict__ raw_x,
    const float* __restrict__ a, const float* __restrict__ mask,
    const int* __restrict__ node_index, const int* __restrict__ type_index,
    float* __restrict__ out, int B, int N)
{
    int b = blockIdx.x / SPLITS;
    int chunk = blockIdx.x - b * SPLITS;
    int tid = threadIdx.x;
    int lane = tid & 31, warp = tid >> 5;
    int g = lane & 15;              // float4 column index within row
    int grp = lane >> 4;            // which 16-row subgroup

    __shared__ float4 w4s[16];      // a[t, 64:128]
    __shared__ float c_sh;          // dot(x[b,node,:], a[t,0:64])
    __shared__ float red_m[NWARPS], red_s[NWARPS];

    int t = type_index[b];
    if (tid < 16)
        w4s[tid] = reinterpret_cast<const float4*>(a + t * 128 + 64)[tid];
    if (tid < 32) {
        const float* xr = x + (size_t)b * N * 64 + (size_t)node_index[0] * 64;
        const float* wa = a + t * 128;
        float s = xr[lane] * wa[lane] + xr[lane + 32] * wa[lane + 32];
        #pragma unroll
        for (int off = 16; off; off >>= 1)
            s += __shfl_xor_sync(0xffffffffu, s, off);
        if (lane == 0) c_sh = s;
    }
    __syncthreads();
    float c = c_sh;
    float4 w = w4s[g];              // per-lane weight fragment (registers)

    int rows = (N + SPLITS - 1) / SPLITS;
    int n0 = chunk * rows;
    int n1 = min(n0 + rows, N);

    const float4* base = reinterpret_cast<const float4*>(raw_x + (size_t)b * N * 64);

    float m = NEGV, s = 0.0f;

    for (int tile = n0 + warp * 32; tile < n1; tile += NWARPS * 32) {
        int rbase = tile + grp * 16;
        float acc[16];
        // 16 independent loads: lane g reads col g of rows rbase..rbase+15
        #pragma unroll
        for (int p = 0; p < 16; p++) {
            int r = min(rbase + p, N - 1);
            float4 v = base[(size_t)r * 16 + g];
            acc[p] = v.x * w.x + v.y * w.y + v.z * w.z + v.w * w.w;
        }
        // multi-output recursive-halving reduce across the 16-lane group:
        // after all steps, lane g holds the full dot of row rbase+g.
        #pragma unroll
        for (int i = 0; i < 8; i++) {
            float send = (g & 8) ? acc[i] : acc[i + 8];
            float recv = __shfl_xor_sync(0xffffffffu, send, 8);
            acc[i] = ((g & 8) ? acc[i + 8] : acc[i]) + recv;
        }
        #pragma unroll
        for (int i = 0; i < 4; i++) {
            float send = (g & 4) ? acc[i] : acc[i + 4];
            float recv = __shfl_xor_sync(0xffffffffu, send, 4);
            acc[i] = ((g & 4) ? acc[i + 4] : acc[i]) + recv;
        }
        #pragma unroll
        for (int i = 0; i < 2; i++) {
            float send = (g & 2) ? acc[i] : acc[i + 2];
            float recv = __shfl_xor_sync(0xffffffffu, send, 2);
            acc[i] = ((g & 2) ? acc[i + 2] : acc[i]) + recv;
        }
        {
            float send = (g & 1) ? acc[0] : acc[1];
            float recv = __shfl_xor_sync(0xffffffffu, send, 1);
            acc[0] = ((g & 1) ? acc[1] : acc[0]) + recv;
        }

        int nh = tile + lane;       // row owned by this lane
        if (nh < n1) {
            float e = acc[0] + c;
            e = e > 0.0f ? e : LEAKY * e;
            float val = (mask[nh] > 0.0f) ? e : NEGV;   // coalesced
            out[(size_t)b * N + nh] = val;              // coalesced
            float mn = fmaxf(m, val);
            s = s * __expf(m - mn) + __expf(val - mn);
            m = mn;
        }
    }

    // warp reduce (m, s)
    #pragma unroll
    for (int off = 16; off; off >>= 1) {
        float mo = __shfl_xor_sync(0xffffffffu, m, off);
        float so = __shfl_xor_sync(0xffffffffu, s, off);
        sm_combine(m, s, mo, so);
    }
    if (lane == 0) { red_m[warp] = m; red_s[warp] = s; }
    __syncthreads();
    if (tid < 32) {
        m = (lane < NWARPS) ? red_m[lane] : NEGV;
        s = (lane < NWARPS) ? red_s[lane] : 0.0f;
        #pragma unroll
        for (int off = 16; off; off >>= 1) {
            float mo = __shfl_xor_sync(0xffffffffu, m, off);
            float so = __shfl_xor_sync(0xffffffffu, s, off);
            sm_combine(m, s, mo, so);
        }
        if (lane == 0) g_partials[b * SPLITS + chunk] = make_float2(m, s);
    }
}

__global__ void pass2(int B)
{
    int b = threadIdx.x;
    if (b >= B) return;
    float m = NEGV, s = 0.0f;
    #pragma unroll
    for (int i = 0; i < SPLITS; i++) {
        float2 p = g_partials[b * SPLITS + i];
        sm_combine(m, s, p.x, p.y);
    }
    g_final[b] = make_float2(m, 1.0f / s);
}

__global__ __launch_bounds__(THREADS) void pass3(
    const float* __restrict__ mask, float* __restrict__ out, int B, int N)
{
    int b = blockIdx.x / SPLITS;
    int chunk = blockIdx.x - b * SPLITS;
    int tid = threadIdx.x;
    float2 f = g_final[b];

    int rows = (N + SPLITS - 1) / SPLITS;
    int n0 = chunk * rows;
    int n1 = min(n0 + rows, N);

    for (int n = n0 + tid; n < n1; n += THREADS) {
        size_t idx = (size_t)b * N + n;
        float v = out[idx];
        out[idx] = __expf(v - f.x) * f.y * mask[n];
    }
}

extern "C" void kernel_launch(void* const* d_in, const int* in_sizes, int n_in,
                              void* d_out, int out_size)
{
    const float* x          = (const float*)d_in[0];
    const float* raw_x      = (const float*)d_in[1];
    const float* a          = (const float*)d_in[2];
    const float* mask       = (const float*)d_in[3];
    const int*   node_index = (const int*)d_in[4];
    const int*   type_index = (const int*)d_in[5];
    float* out = (float*)d_out;

    int N = in_sizes[3];   // adj_mask element count
    int B = in_sizes[5];   // type_index element count

    pass1<<<B * SPLITS, THREADS>>>(x, raw_x, a, mask, node_index, type_index, out, B, N);
    pass2<<<1, 256>>>(B);
    pass3<<<B * SPLITS, THREADS>>>(mask, out, B, N);
}

// round 4
// speedup vs baseline: 1.7358x; 1.1691x over previous
#include <cuda_runtime.h>
#include <cuda_bf16.h>

#define NEGV (-9000000000000000.0f)
#define LEAKY 0.01f
#define TPB 1024
#define NW (TPB / 32)
#define LMAX 10

__device__ __forceinline__ void sm_combine(float& m, float& s, float mo, float so) {
    float mn = fmaxf(m, mo);
    s = s * __expf(m - mn) + so * __expf(mo - mn);
    m = mn;
}

__global__ __launch_bounds__(TPB) void fused(
    const float* __restrict__ x, const float* __restrict__ raw_x,
    const float* __restrict__ a, const float* __restrict__ mask,
    const int* __restrict__ node_index, const int* __restrict__ type_index,
    float* __restrict__ out, int N)
{
    int b = blockIdx.x;
    int tid = threadIdx.x;
    int lane = tid & 31, warp = tid >> 5;
    int g = lane & 15;              // float4 column within row
    int grp = lane >> 4;            // 16-row subgroup

    __shared__ float4 w4s[16];      // a[t, 64:128]
    __shared__ float c_sh;          // dot(x[b,node,:], a[t,0:64])
    __shared__ float red_m[NW], red_s[NW];
    __shared__ float2 fin;

    int t = type_index[b];
    if (tid < 16)
        w4s[tid] = reinterpret_cast<const float4*>(a + t * 128 + 64)[tid];
    if (tid >= 32 && tid < 64) {
        int l = tid - 32;
        const float* xr = x + (size_t)b * N * 64 + (size_t)node_index[0] * 64;
        const float* wa = a + t * 128;
        float s = xr[l] * wa[l] + xr[l + 32] * wa[l + 32];
        #pragma unroll
        for (int off = 16; off; off >>= 1)
            s += __shfl_xor_sync(0xffffffffu, s, off);
        if (l == 0) c_sh = s;
    }
    __syncthreads();
    float c = c_sh;
    float4 w = w4s[g];

    const float4* base = reinterpret_cast<const float4*>(raw_x + (size_t)b * N * 64);

    int ntiles = (N + TPB - 1) / TPB;
    float m = NEGV, s = 0.0f;
    float logit[LMAX];

    // ---------- phase A: logits into registers + online (m,s) ----------
    #pragma unroll
    for (int it = 0; it < LMAX; it++) {
        if (it >= ntiles) break;
        int rbase = it * TPB + warp * 32 + grp * 16;
        float acc[16];
        #pragma unroll
        for (int p = 0; p < 16; p++) {
            int r = min(rbase + p, N - 1);
            float4 v = base[(size_t)r * 16 + g];
            acc[p] = v.x * w.x + v.y * w.y + v.z * w.z + v.w * w.w;
        }
        // multi-output recursive-halving: lane g ends with dot of row rbase+g-ish
        #pragma unroll
        for (int i = 0; i < 8; i++) {
            float send = (g & 8) ? acc[i] : acc[i + 8];
            float recv = __shfl_xor_sync(0xffffffffu, send, 8);
            acc[i] = ((g & 8) ? acc[i + 8] : acc[i]) + recv;
        }
        #pragma unroll
        for (int i = 0; i < 4; i++) {
            float send = (g & 4) ? acc[i] : acc[i + 4];
            float recv = __shfl_xor_sync(0xffffffffu, send, 4);
            acc[i] = ((g & 4) ? acc[i + 4] : acc[i]) + recv;
        }
        #pragma unroll
        for (int i = 0; i < 2; i++) {
            float send = (g & 2) ? acc[i] : acc[i + 2];
            float recv = __shfl_xor_sync(0xffffffffu, send, 2);
            acc[i] = ((g & 2) ? acc[i + 2] : acc[i]) + recv;
        }
        {
            float send = (g & 1) ? acc[0] : acc[1];
            float recv = __shfl_xor_sync(0xffffffffu, send, 1);
            acc[0] = ((g & 1) ? acc[1] : acc[0]) + recv;
        }

        int nh = it * TPB + warp * 32 + lane;
        float val = NEGV;
        if (nh < N) {
            float e = acc[0] + c;
            e = e > 0.0f ? e : LEAKY * e;
            val = (mask[nh] > 0.0f) ? e : NEGV;
            float mn = fmaxf(m, val);
            s = s * __expf(m - mn) + __expf(val - mn);
            m = mn;
        }
        logit[it] = val;
    }
    // overflow tiles (N > LMAX*TPB): spill to out as scratch
    for (int it = LMAX; it < ntiles; it++) {
        int rbase = it * TPB + warp * 32 + grp * 16;
        float acc[16];
        #pragma unroll
        for (int p = 0; p < 16; p++) {
            int r = min(rbase + p, N - 1);
            float4 v = base[(size_t)r * 16 + g];
            acc[p] = v.x * w.x + v.y * w.y + v.z * w.z + v.w * w.w;
        }
        #pragma unroll
        for (int i = 0; i < 8; i++) {
            float send = (g & 8) ? acc[i] : acc[i + 8];
            float recv = __shfl_xor_sync(0xffffffffu, send, 8);
            acc[i] = ((g & 8) ? acc[i + 8] : acc[i]) + recv;
        }
        #pragma unroll
        for (int i = 0; i < 4; i++) {
            float send = (g & 4) ? acc[i] : acc[i + 4];
            float recv = __shfl_xor_sync(0xffffffffu, send, 4);
            acc[i] = ((g & 4) ? acc[i + 4] : acc[i]) + recv;
        }
        #pragma unroll
        for (int i = 0; i < 2; i++) {
            float send = (g & 2) ? acc[i] : acc[i + 2];
            float recv = __shfl_xor_sync(0xffffffffu, send, 2);
            acc[i] = ((g & 2) ? acc[i + 2] : acc[i]) + recv;
        }
        {
            float send = (g & 1) ? acc[0] : acc[1];
            float recv = __shfl_xor_sync(0xffffffffu, send, 1);
            acc[0] = ((g & 1) ? acc[1] : acc[0]) + recv;
        }
        int nh = it * TPB + warp * 32 + lane;
        if (nh < N) {
            float e = acc[0] + c;
            e = e > 0.0f ? e : LEAKY * e;
            float val = (mask[nh] > 0.0f) ? e : NEGV;
            out[(size_t)b * N + nh] = val;
            float mn = fmaxf(m, val);
            s = s * __expf(m - mn) + __expf(val - mn);
            m = mn;
        }
    }

    // ---------- block reduce (m, s) ----------
    #pragma unroll
    for (int off = 16; off; off >>= 1) {
        float mo = __shfl_xor_sync(0xffffffffu, m, off);
        float so = __shfl_xor_sync(0xffffffffu, s, off);
        sm_combine(m, s, mo, so);
    }
    if (lane == 0) { red_m[warp] = m; red_s[warp] = s; }
    __syncthreads();
    if (tid < 32) {
        m = (lane < NW) ? red_m[lane] : NEGV;
        s = (lane < NW) ? red_s[lane] : 0.0f;
        #pragma unroll
        for (int off = 16; off; off >>= 1) {
            float mo = __shfl_xor_sync(0xffffffffu, m, off);
            float so = __shfl_xor_sync(0xffffffffu, s, off);
            sm_combine(m, s, mo, so);
        }
        if (lane == 0) fin = make_float2(m, 1.0f / s);
    }
    __syncthreads();
    float M = fin.x, invS = fin.y;

    // ---------- phase B: write finals straight from registers ----------
    #pragma unroll
    for (int it = 0; it < LMAX; it++) {
        if (it >= ntiles) break;
        int nh = it * TPB + warp * 32 + lane;
        if (nh < N)
            out[(size_t)b * N + nh] = __expf(logit[it] - M) * invS * mask[nh];
    }
    for (int it = LMAX; it < ntiles; it++) {
        int nh = it * TPB + warp * 32 + lane;
        if (nh < N) {
            size_t idx = (size_t)b * N + nh;
            float v = out[idx];
            out[idx] = __expf(v - M) * invS * mask[nh];
        }
    }
}

extern "C" void kernel_launch(void* const* d_in, const int* in_sizes, int n_in,
                              void* d_out, int out_size)
{
    const float* x          = (const float*)d_in[0];
    const float* raw_x      = (const float*)d_in[1];
    const float* a          = (const float*)d_in[2];
    const float* mask       = (const float*)d_in[3];
    const int*   node_index = (const int*)d_in[4];
    const int*   type_index = (const int*)d_in[5];
    float* out = (float*)d_out;

    int N = in_sizes[3];   // adj_mask element count
    int B = in_sizes[5];   // type_index element count

    fused<<<B, TPB>>>(x, raw_x, a, mask, node_index, type_index, out, N);
}